// round 8
// baseline (speedup 1.0000x reference)
#include <cuda_runtime.h>
#include <cuda_bf16.h>
#include <math.h>

#define N_ANCH   102400
#define FMP      320
#define NCLS     80
#define TOPK     1000
#define CAP      4096
#define NBINS    65536

// libdevice precise expf — the exact function XLA:GPU links for HLO exp(f32).
// Declaring it directly bypasses any --use_fast_math header remapping.
extern "C" __device__ float __nv_expf(float);

// ---------------- device scratch (no allocations allowed) ----------------
__device__ unsigned int        d_hist[NBINS];
__device__ int                 d_count;
__device__ int                 d_thresh;
__device__ unsigned int        d_sbits[N_ANCH];
__device__ unsigned char       d_label[N_ANCH];
__device__ unsigned long long  d_keys[CAP];
__device__ float               d_boxes[TOPK * 4];
__device__ int                 d_tlab[TOPK];
__device__ unsigned int        d_mask[TOPK * 32];

// XLA LogisticExpander (current): logistic(x) = 1 / (1 + exp(-x)),
// exp -> __nv_expf, divide -> div.rn. Bit-exact replication.
__device__ __forceinline__ float xsig(float x) {
    return __fdiv_rn(1.0f, __fadd_rn(1.0f, __nv_expf(-x)));
}
__device__ __forceinline__ float xfused(float h, float K) {
    return __fsqrt_rn(__fmul_rn(xsig(h), K));
}

// ---------------- K0: clear histogram + counter ----------------
__global__ void k_clear() {
    int i = blockIdx.x * blockDim.x + threadIdx.x;
    if (i < NBINS) d_hist[i] = 0u;
    if (i == 0) d_count = 0;
}

// ---------------- K1: per-anchor score/label + histogram ----------------
// Phase 1: warp-max of raw hmp (m1). Phase 2: evaluate fused only for classes
// within 1e-4 of m1 (covers rounding plateaus / exp non-monotonicity), take
// max fused with lowest-index tie-break == JAX max/argmax over fused values.
__global__ void k_score(const float* __restrict__ hmp,
                        const float* __restrict__ iou) {
    int a    = (blockIdx.x << 3) + (threadIdx.x >> 5);   // one warp per anchor
    int lane = threadIdx.x & 31;
    const float4* row = reinterpret_cast<const float4*>(hmp) + (size_t)a * 20;

    float4 v = make_float4(0.f, 0.f, 0.f, 0.f);
    float m = __int_as_float(0xff800000);   // -inf
    if (lane < 20) {
        v = row[lane];
        m = fmaxf(fmaxf(v.x, v.y), fmaxf(v.z, v.w));
    }
    #pragma unroll
    for (int off = 16; off; off >>= 1)
        m = fmaxf(m, __shfl_xor_sync(0xffffffffu, m, off));

    float K   = xsig(iou[a]);               // broadcast load, warp-uniform
    float thr = m - 1e-4f;

    float best = __int_as_float(0xff800000);
    int   bi   = 0x7FFFFFFF;
    if (lane < 20) {
        int b = lane * 4;
        if (v.x >= thr) { float f = xfused(v.x, K); if (f > best) { best = f; bi = b;     } }
        if (v.y >= thr) { float f = xfused(v.y, K); if (f > best) { best = f; bi = b + 1; } }
        if (v.z >= thr) { float f = xfused(v.z, K); if (f > best) { best = f; bi = b + 2; } }
        if (v.w >= thr) { float f = xfused(v.w, K); if (f > best) { best = f; bi = b + 3; } }
    }
    #pragma unroll
    for (int off = 16; off; off >>= 1) {
        float of = __shfl_xor_sync(0xffffffffu, best, off);
        int   oi = __shfl_xor_sync(0xffffffffu, bi,   off);
        if (of > best || (of == best && oi < bi)) { best = of; bi = oi; }
    }

    if (lane == 0) {
        unsigned bits = __float_as_uint(best);   // best > 0 => monotone pattern
        d_sbits[a] = bits;
        d_label[a] = (unsigned char)bi;
        atomicAdd(&d_hist[bits >> 16], 1u);
    }
}

// ---------------- K2: find 16-bit threshold bin ----------------
__global__ void k_scan() {
    __shared__ unsigned int ps[1024];
    __shared__ unsigned int suf[1024];
    int tid = threadIdx.x;
    unsigned base = tid * 64;
    unsigned s = 0;
    for (int k = 0; k < 64; ++k) s += d_hist[base + k];
    ps[tid]  = s;
    suf[tid] = s;
    __syncthreads();
    for (int off = 1; off < 1024; off <<= 1) {
        unsigned vv = (tid + off < 1024) ? suf[tid + off] : 0u;
        __syncthreads();
        suf[tid] += vv;
        __syncthreads();
    }
    unsigned above = suf[tid] - ps[tid];          // strictly above my range
    if (above < TOPK && suf[tid] >= TOPK) {       // crossing bin in my range
        unsigned cum = above;
        for (int k = 63; k >= 0; --k) {
            cum += d_hist[base + k];
            if (cum >= TOPK) { d_thresh = (int)(base + k); break; }
        }
    }
}

// ---------------- K3: compact candidates (bins >= threshold) ----------------
__global__ void k_compact() {
    int a = blockIdx.x * blockDim.x + threadIdx.x;
    if (a >= N_ANCH) return;
    unsigned bits = d_sbits[a];
    if ((int)(bits >> 16) >= d_thresh) {
        int pos = atomicAdd(&d_count, 1);
        if (pos < CAP) {
            unsigned long long key =
                ((unsigned long long)bits << 32) | (unsigned long long)(0xFFFFFFFFu - (unsigned)a);
            d_keys[pos] = ~key;   // ascending on ~key == descending on key
        }
    }
}

// ---------------- K4: bitonic sort (<=4096) + decode top-1000 ----------------
__global__ void k_sort_decode(const float* __restrict__ reg, float* __restrict__ out) {
    __shared__ unsigned long long sk[CAP];
    int tid = threadIdx.x;
    int M = d_count; if (M > CAP) M = CAP;
    for (int i = tid; i < CAP; i += 1024)
        sk[i] = (i < M) ? d_keys[i] : 0xFFFFFFFFFFFFFFFFull;
    __syncthreads();

    for (int k = 2; k <= CAP; k <<= 1) {
        for (int j = k >> 1; j > 0; j >>= 1) {
            for (int p = tid; p < (CAP >> 1); p += 1024) {
                int i1 = ((p & ~(j - 1)) << 1) | (p & (j - 1));
                int i2 = i1 | j;
                bool up = ((i1 & k) == 0);
                unsigned long long va = sk[i1], vb = sk[i2];
                if ((va > vb) == up) { sk[i1] = vb; sk[i2] = va; }
            }
            __syncthreads();
        }
    }

    if (tid < TOPK) {
        unsigned long long key = ~sk[tid];
        unsigned bits = (unsigned)(key >> 32);
        unsigned aidx = 0xFFFFFFFFu - (unsigned)(key & 0xFFFFFFFFull);
        float score = __uint_as_float(bits);
        int   lab   = (int)d_label[aidx];

        const float CLAMPF = 6.907755278982137f;   // log(1000)
        float4 r4 = reinterpret_cast<const float4*>(reg)[aidx];
        float e0 = __nv_expf(fminf(r4.x, CLAMPF));
        float e1 = __nv_expf(fminf(r4.y, CLAMPF));
        float e2 = __nv_expf(fminf(r4.z, CLAMPF));
        float e3 = __nv_expf(fminf(r4.w, CLAMPF));
        float ax = (float)(aidx % FMP);
        float ay = (float)(aidx / FMP);
        float b0 = fminf(1.0f, fmaxf(0.0f, __fdiv_rn(__fmul_rn(__fadd_rn(ax, -e0), 4.0f), 1280.0f)));
        float b1 = fminf(1.0f, fmaxf(0.0f, __fdiv_rn(__fmul_rn(__fadd_rn(ay, -e1), 4.0f), 1280.0f)));
        float b2 = fminf(1.0f, fmaxf(0.0f, __fdiv_rn(__fmul_rn(__fadd_rn(ax,  e2), 4.0f), 1280.0f)));
        float b3 = fminf(1.0f, fmaxf(0.0f, __fdiv_rn(__fmul_rn(__fadd_rn(ay,  e3), 4.0f), 1280.0f)));

        out[tid]              = score;
        out[TOPK + tid]       = (float)lab;
        out[2 * TOPK + 4 * tid + 0] = b0;
        out[2 * TOPK + 4 * tid + 1] = b1;
        out[2 * TOPK + 4 * tid + 2] = b2;
        out[2 * TOPK + 4 * tid + 3] = b3;
        d_boxes[4 * tid + 0] = b0;
        d_boxes[4 * tid + 1] = b1;
        d_boxes[4 * tid + 2] = b2;
        d_boxes[4 * tid + 3] = b3;
        d_tlab[tid] = lab;
    }
}

// ---------------- K5: suppression bitmask (j > i, same class, IoU > 0.6) ----
__global__ void k_mask() {
    int i = blockIdx.x;            // 0..999
    int j = threadIdx.x;           // 0..1023
    float x1i = d_boxes[4 * i + 0], y1i = d_boxes[4 * i + 1];
    float x2i = d_boxes[4 * i + 2], y2i = d_boxes[4 * i + 3];
    float ai  = __fmul_rn(__fadd_rn(x2i, -x1i), __fadd_rn(y2i, -y1i));
    int li = d_tlab[i];

    bool sup = false;
    if (j < TOPK && j > i && d_tlab[j] == li) {
        float x1j = d_boxes[4 * j + 0], y1j = d_boxes[4 * j + 1];
        float x2j = d_boxes[4 * j + 2], y2j = d_boxes[4 * j + 3];
        float aj  = __fmul_rn(__fadd_rn(x2j, -x1j), __fadd_rn(y2j, -y1j));
        float w = fmaxf(1e-10f, __fadd_rn(fminf(x2i, x2j), -fmaxf(x1i, x1j)));
        float h = fmaxf(1e-10f, __fadd_rn(fminf(y2i, y2j), -fmaxf(y1i, y1j)));
        float inter = __fmul_rn(w, h);
        float den = __fadd_rn(__fadd_rn(__fadd_rn(ai, aj), -inter), 1e-10f);
        float iou = __fdiv_rn(inter, den);
        sup = (iou > 0.6f);
    }
    unsigned b = __ballot_sync(0xffffffffu, sup);
    if ((threadIdx.x & 31) == 0) d_mask[i * 32 + (threadIdx.x >> 5)] = b;
}

// ---------------- K6: greedy NMS (chunked serial + parallel cross-OR) ------
__global__ void k_nms(float* __restrict__ out) {
    __shared__ unsigned int remv[32];
    __shared__ unsigned int keepw[32];
    int tid = threadIdx.x;
    int w = tid >> 5, ln = tid & 31;
    if (tid < 32) remv[tid] = 0u;
    __syncthreads();

    for (int c = 0; c < 32; ++c) {
        int row = c * 32 + ln;
        unsigned cval = 0u;                         // prefetch cross-chunk words
        if (w > c && row < TOPK) cval = d_mask[row * 32 + w];

        if (w == 0) {
            unsigned mself = (row < TOPK) ? d_mask[row * 32 + c] : 0u;
            unsigned r = remv[c];
            unsigned mv[32];
            #pragma unroll
            for (int t = 0; t < 32; ++t) mv[t] = __shfl_sync(0xffffffffu, mself, t);
            #pragma unroll
            for (int t = 0; t < 32; ++t) r |= mv[t] & (((r >> t) & 1u) - 1u);
            if (ln == 0) keepw[c] = ~r;
        }
        __syncthreads();

        if (w > c) {
            unsigned kv = keepw[c];
            unsigned vv = ((kv >> ln) & 1u) ? cval : 0u;
            #pragma unroll
            for (int off = 16; off; off >>= 1) vv |= __shfl_xor_sync(0xffffffffu, vv, off);
            if (ln == 0) remv[w] |= vv;
        }
        __syncthreads();
    }

    if (tid < TOPK)
        out[6 * TOPK + tid] = (float)((keepw[tid >> 5] >> (tid & 31)) & 1u);
}

// ---------------- launch ----------------
extern "C" void kernel_launch(void* const* d_in, const int* in_sizes, int n_in,
                              void* d_out, int out_size) {
    const float* hmp = (const float*)d_in[0];
    const float* reg = (const float*)d_in[1];
    const float* iou = (const float*)d_in[2];
    float* out = (float*)d_out;

    k_clear<<<64, 1024>>>();
    k_score<<<N_ANCH / 8, 256>>>(hmp, iou);
    k_scan<<<1, 1024>>>();
    k_compact<<<(N_ANCH + 255) / 256, 256>>>();
    k_sort_decode<<<1, 1024>>>(reg, out);
    k_mask<<<TOPK, 1024>>>();
    k_nms<<<1, 1024>>>(out);
}

// round 9
// speedup vs baseline: 1.4957x; 1.4957x over previous
#include <cuda_runtime.h>
#include <cuda_bf16.h>
#include <math.h>

#define N_ANCH   102400
#define FMP      320
#define NCLS     80
#define TOPK     1000
#define CAP      4096
#define NBINS    65536

// libdevice precise expf — the exact function XLA:GPU links for HLO exp(f32).
extern "C" __device__ float __nv_expf(float);

// ---------------- device scratch (no allocations allowed) ----------------
__device__ unsigned int                    d_hist[NBINS];
__device__ int                             d_count;
__device__ int                             d_thresh;
__device__ __align__(16) unsigned int      d_sbits[N_ANCH];
__device__ unsigned char                   d_label[N_ANCH];
__device__ unsigned long long              d_keys[CAP];
__device__ float                           d_boxes[TOPK * 4];
__device__ int                             d_tlab[TOPK];
__device__ unsigned int                    d_mask[TOPK * 32];

// XLA LogisticExpander: logistic(x) = 1/(1+exp(-x)), exp->__nv_expf, div->rn.
__device__ __forceinline__ float xsig(float x) {
    return __fdiv_rn(1.0f, __fadd_rn(1.0f, __nv_expf(-x)));
}
__device__ __forceinline__ float xfused(float h, float K) {
    return __fsqrt_rn(__fmul_rn(xsig(h), K));
}

// ---------------- K1: per-anchor score/label + histogram ----------------
__global__ void k_score(const float* __restrict__ hmp,
                        const float* __restrict__ iou) {
    int a    = (blockIdx.x << 3) + (threadIdx.x >> 5);   // one warp per anchor
    int lane = threadIdx.x & 31;
    const float4* row = reinterpret_cast<const float4*>(hmp) + (size_t)a * 20;

    float4 v = make_float4(0.f, 0.f, 0.f, 0.f);
    float m = __int_as_float(0xff800000);
    if (lane < 20) {
        v = row[lane];
        m = fmaxf(fmaxf(v.x, v.y), fmaxf(v.z, v.w));
    }
    #pragma unroll
    for (int off = 16; off; off >>= 1)
        m = fmaxf(m, __shfl_xor_sync(0xffffffffu, m, off));

    float K   = xsig(iou[a]);
    float thr = m - 1e-4f;

    float best = __int_as_float(0xff800000);
    int   bi   = 0x7FFFFFFF;
    if (lane < 20) {
        int b = lane * 4;
        if (v.x >= thr) { float f = xfused(v.x, K); if (f > best) { best = f; bi = b;     } }
        if (v.y >= thr) { float f = xfused(v.y, K); if (f > best) { best = f; bi = b + 1; } }
        if (v.z >= thr) { float f = xfused(v.z, K); if (f > best) { best = f; bi = b + 2; } }
        if (v.w >= thr) { float f = xfused(v.w, K); if (f > best) { best = f; bi = b + 3; } }
    }
    #pragma unroll
    for (int off = 16; off; off >>= 1) {
        float of = __shfl_xor_sync(0xffffffffu, best, off);
        int   oi = __shfl_xor_sync(0xffffffffu, bi,   off);
        if (of > best || (of == best && oi < bi)) { best = of; bi = oi; }
    }

    if (lane == 0) {
        unsigned bits = __float_as_uint(best);
        d_sbits[a] = bits;
        d_label[a] = (unsigned char)bi;
        atomicAdd(&d_hist[bits >> 16], 1u);
    }
}

// ---------------- K2: find 16-bit threshold bin ----------------
__global__ void k_scan() {
    __shared__ unsigned int ps[1024];
    __shared__ unsigned int suf[1024];
    int tid = threadIdx.x;
    unsigned base = tid * 64;
    const uint4* h4 = reinterpret_cast<const uint4*>(d_hist + base);
    unsigned s = 0;
    #pragma unroll
    for (int k = 0; k < 16; ++k) {
        uint4 vv = h4[k];
        s += vv.x + vv.y + vv.z + vv.w;
    }
    ps[tid]  = s;
    suf[tid] = s;
    __syncthreads();
    for (int off = 1; off < 1024; off <<= 1) {
        unsigned vv = (tid + off < 1024) ? suf[tid + off] : 0u;
        __syncthreads();
        suf[tid] += vv;
        __syncthreads();
    }
    unsigned above = suf[tid] - ps[tid];
    if (above < TOPK && suf[tid] >= TOPK) {
        unsigned cum = above;
        for (int k = 63; k >= 0; --k) {
            cum += d_hist[base + k];
            if (cum >= TOPK) { d_thresh = (int)(base + k); break; }
        }
    }
}

// ---------------- K3: compact candidates (vectorized, 1 wave) -------------
__global__ void k_compact() {
    int t = blockIdx.x * blockDim.x + threadIdx.x;   // 0..25599
    uint4 s = reinterpret_cast<const uint4*>(d_sbits)[t];
    int th = d_thresh;
    unsigned a = (unsigned)t * 4u;
    #pragma unroll
    for (int q = 0; q < 4; ++q) {
        unsigned bits = (q == 0) ? s.x : (q == 1) ? s.y : (q == 2) ? s.z : s.w;
        if ((int)(bits >> 16) >= th) {
            int pos = atomicAdd(&d_count, 1);
            if (pos < CAP) {
                unsigned long long key =
                    ((unsigned long long)bits << 32) |
                    (unsigned long long)(0xFFFFFFFFu - (a + q));
                d_keys[pos] = ~key;
            }
        }
    }
}

// ---------------- K4: rank-by-counting + decode top-1000 ------------------
// 64 blocks x 256 threads; 4 threads per candidate; exact since keys distinct.
__global__ void k_rank_decode(const float* __restrict__ reg,
                              float* __restrict__ out) {
    __shared__ unsigned long long ch[256];
    int M = d_count; if (M > CAP) M = CAP;
    int cand = blockIdx.x * 64 + (threadIdx.x >> 2);
    int sub  = threadIdx.x & 3;
    unsigned long long key = (cand < M) ? d_keys[cand] : 0xFFFFFFFFFFFFFFFFull;

    int rank = 0;
    for (int base = 0; base < M; base += 256) {
        int idx = base + threadIdx.x;
        ch[threadIdx.x] = (idx < M) ? d_keys[idx] : 0xFFFFFFFFFFFFFFFFull;
        __syncthreads();
        int lim = M - base; if (lim > 256) lim = 256;
        for (int k = sub; k < lim; k += 4) rank += (ch[k] < key) ? 1 : 0;
        __syncthreads();
    }
    rank += __shfl_xor_sync(0xffffffffu, rank, 1);
    rank += __shfl_xor_sync(0xffffffffu, rank, 2);

    if (sub == 0 && cand < M && rank < TOPK) {
        unsigned long long k0 = ~key;
        unsigned bits = (unsigned)(k0 >> 32);
        unsigned aidx = 0xFFFFFFFFu - (unsigned)(k0 & 0xFFFFFFFFull);
        float score = __uint_as_float(bits);
        int   lab   = (int)d_label[aidx];

        const float CLAMPF = 6.907755278982137f;   // log(1000)
        float4 r4 = reinterpret_cast<const float4*>(reg)[aidx];
        float e0 = __nv_expf(fminf(r4.x, CLAMPF));
        float e1 = __nv_expf(fminf(r4.y, CLAMPF));
        float e2 = __nv_expf(fminf(r4.z, CLAMPF));
        float e3 = __nv_expf(fminf(r4.w, CLAMPF));
        float ax = (float)(aidx % FMP);
        float ay = (float)(aidx / FMP);
        float b0 = fminf(1.0f, fmaxf(0.0f, __fdiv_rn(__fmul_rn(__fadd_rn(ax, -e0), 4.0f), 1280.0f)));
        float b1 = fminf(1.0f, fmaxf(0.0f, __fdiv_rn(__fmul_rn(__fadd_rn(ay, -e1), 4.0f), 1280.0f)));
        float b2 = fminf(1.0f, fmaxf(0.0f, __fdiv_rn(__fmul_rn(__fadd_rn(ax,  e2), 4.0f), 1280.0f)));
        float b3 = fminf(1.0f, fmaxf(0.0f, __fdiv_rn(__fmul_rn(__fadd_rn(ay,  e3), 4.0f), 1280.0f)));

        out[rank]              = score;
        out[TOPK + rank]       = (float)lab;
        out[2 * TOPK + 4 * rank + 0] = b0;
        out[2 * TOPK + 4 * rank + 1] = b1;
        out[2 * TOPK + 4 * rank + 2] = b2;
        out[2 * TOPK + 4 * rank + 3] = b3;
        d_boxes[4 * rank + 0] = b0;
        d_boxes[4 * rank + 1] = b1;
        d_boxes[4 * rank + 2] = b2;
        d_boxes[4 * rank + 3] = b3;
        d_tlab[rank] = lab;
    }
}

// ---------------- K5: suppression bitmask ---------------------------------
// Only words w >= (i>>5) are ever read by NMS; lower warps retire instantly.
// Predicate rn32(inter/den) > 0.6f replicated exactly via double quotient
// against the rounding midpoint of 0.6f (no f32 div sequence).
__global__ void k_mask() {
    int i = blockIdx.x;                    // 0..999
    int w = threadIdx.x >> 5;
    if (w < (i >> 5)) return;              // whole-warp early retire
    int j = threadIdx.x;

    float x1i = d_boxes[4 * i + 0], y1i = d_boxes[4 * i + 1];
    float x2i = d_boxes[4 * i + 2], y2i = d_boxes[4 * i + 3];
    float ai  = __fmul_rn(__fadd_rn(x2i, -x1i), __fadd_rn(y2i, -y1i));
    int li = d_tlab[i];

    bool sup = false;
    if (j < TOPK && j > i && d_tlab[j] == li) {
        float x1j = d_boxes[4 * j + 0], y1j = d_boxes[4 * j + 1];
        float x2j = d_boxes[4 * j + 2], y2j = d_boxes[4 * j + 3];
        float aj  = __fmul_rn(__fadd_rn(x2j, -x1j), __fadd_rn(y2j, -y1j));
        float wd = fmaxf(1e-10f, __fadd_rn(fminf(x2i, x2j), -fmaxf(x1i, x1j)));
        float hd = fmaxf(1e-10f, __fadd_rn(fminf(y2i, y2j), -fmaxf(y1i, y1j)));
        float inter = __fmul_rn(wd, hd);
        float den = __fadd_rn(__fadd_rn(__fadd_rn(ai, aj), -inter), 1e-10f);
        // rn32(inter/den) > 0.6f  <=>  inter/den > midpoint(0.6f, nextup(0.6f))
        sup = ((double)inter / (double)den) > 0.6000000536441802978515625;
    }
    unsigned b = __ballot_sync(0xffffffffu, sup);
    if ((j & 31) == 0) d_mask[i * 32 + w] = b;
}

// ---------------- K6: greedy NMS (sparse serial + parallel cross-OR) ------
__global__ void k_nms(float* __restrict__ out) {
    __shared__ unsigned int remv[32];
    __shared__ unsigned int keepw[32];
    int tid = threadIdx.x;
    int w = tid >> 5, ln = tid & 31;
    if (tid < 32) remv[tid] = 0u;
    __syncthreads();

    for (int c = 0; c < 32; ++c) {
        int row = c * 32 + ln;
        unsigned cval = 0u;                       // prefetch cross-chunk words
        if (w > c && row < TOPK) cval = d_mask[row * 32 + w];

        if (w == 0) {
            unsigned mself = (row < TOPK) ? d_mask[row * 32 + c] : 0u;
            unsigned r = remv[c];
            unsigned act = __ballot_sync(0xffffffffu, mself != 0u);
            while (act) {                          // only rows that suppress
                int t = __ffs(act) - 1;
                act &= act - 1u;
                unsigned mv = __shfl_sync(0xffffffffu, mself, t);
                r |= mv & (((r >> t) & 1u) - 1u);  // apply iff row t kept
            }
            if (ln == 0) keepw[c] = ~r;
        }
        __syncthreads();

        if (w > c) {
            unsigned kv = keepw[c];
            unsigned vv = ((kv >> ln) & 1u) ? cval : 0u;
            #pragma unroll
            for (int off = 16; off; off >>= 1)
                vv |= __shfl_xor_sync(0xffffffffu, vv, off);
            if (ln == 0) remv[w] |= vv;
        }
        __syncthreads();
    }

    if (tid < TOPK)
        out[6 * TOPK + tid] = (float)((keepw[tid >> 5] >> (tid & 31)) & 1u);
}

// ---------------- launch ----------------
extern "C" void kernel_launch(void* const* d_in, const int* in_sizes, int n_in,
                              void* d_out, int out_size) {
    const float* hmp = (const float*)d_in[0];
    const float* reg = (const float*)d_in[1];
    const float* iou = (const float*)d_in[2];
    float* out = (float*)d_out;

    void* hist_ptr = nullptr;
    void* cnt_ptr  = nullptr;
    cudaGetSymbolAddress(&hist_ptr, d_hist);
    cudaGetSymbolAddress(&cnt_ptr,  d_count);
    cudaMemsetAsync(hist_ptr, 0, NBINS * sizeof(unsigned int), 0);
    cudaMemsetAsync(cnt_ptr,  0, sizeof(int), 0);

    k_score<<<N_ANCH / 8, 256>>>(hmp, iou);
    k_scan<<<1, 1024>>>();
    k_compact<<<100, 256>>>();
    k_rank_decode<<<64, 256>>>(reg, out);
    k_mask<<<TOPK, 1024>>>();
    k_nms<<<1, 1024>>>(out);
}

// round 10
// speedup vs baseline: 1.6633x; 1.1121x over previous
#include <cuda_runtime.h>
#include <cuda_bf16.h>
#include <math.h>

#define N_ANCH   102400
#define FMP      320
#define NCLS     80
#define TOPK     1000
#define CAP      4096
#define NBINS    65536
#define NPART    64
#define PBINS    1024
#define NBLK     148

// libdevice precise expf — the exact function XLA:GPU links for HLO exp(f32).
extern "C" __device__ float __nv_expf(float);

// ------- state that must be zero at the start of every replay (ONE memset) --
struct GState {
    unsigned int hist[NBINS];
    unsigned int bars[8];
    int          count;
};
__device__ GState g;

// ------- scratch that is fully written-before-read each replay --------------
__device__ __align__(16) unsigned int      d_sbits[N_ANCH];
__device__ unsigned char                   d_label[N_ANCH];
__device__ unsigned long long              d_keys[CAP];
__device__ float4                          d_boxes4[TOPK];
__device__ int                             d_tlab[TOPK];
__device__ unsigned int                    d_mask[TOPK * 32];
__device__ unsigned int                    d_part[NPART];
__device__ int                             d_thresh;

// XLA LogisticExpander: logistic(x) = 1/(1+exp(-x)), exp->__nv_expf, div->rn.
__device__ __forceinline__ float xsig(float x) {
    return __fdiv_rn(1.0f, __fadd_rn(1.0f, __nv_expf(-x)));
}
__device__ __forceinline__ float xfused(float h, float K) {
    return __fsqrt_rn(__fmul_rn(xsig(h), K));
}

// ---------------- K1: per-anchor score/label + histogram (unchanged) --------
__global__ void k_score(const float* __restrict__ hmp,
                        const float* __restrict__ iou) {
    int a    = (blockIdx.x << 3) + (threadIdx.x >> 5);   // one warp per anchor
    int lane = threadIdx.x & 31;
    const float4* row = reinterpret_cast<const float4*>(hmp) + (size_t)a * 20;

    float4 v = make_float4(0.f, 0.f, 0.f, 0.f);
    float m = __int_as_float(0xff800000);
    if (lane < 20) {
        v = row[lane];
        m = fmaxf(fmaxf(v.x, v.y), fmaxf(v.z, v.w));
    }
    #pragma unroll
    for (int off = 16; off; off >>= 1)
        m = fmaxf(m, __shfl_xor_sync(0xffffffffu, m, off));

    float K   = xsig(iou[a]);
    float thr = m - 1e-4f;

    float best = __int_as_float(0xff800000);
    int   bi   = 0x7FFFFFFF;
    if (lane < 20) {
        int b = lane * 4;
        if (v.x >= thr) { float f = xfused(v.x, K); if (f > best) { best = f; bi = b;     } }
        if (v.y >= thr) { float f = xfused(v.y, K); if (f > best) { best = f; bi = b + 1; } }
        if (v.z >= thr) { float f = xfused(v.z, K); if (f > best) { best = f; bi = b + 2; } }
        if (v.w >= thr) { float f = xfused(v.w, K); if (f > best) { best = f; bi = b + 3; } }
    }
    #pragma unroll
    for (int off = 16; off; off >>= 1) {
        float of = __shfl_xor_sync(0xffffffffu, best, off);
        int   oi = __shfl_xor_sync(0xffffffffu, bi,   off);
        if (of > best || (of == best && oi < bi)) { best = of; bi = oi; }
    }

    if (lane == 0) {
        unsigned bits = __float_as_uint(best);
        d_sbits[a] = bits;
        d_label[a] = (unsigned char)bi;
        atomicAdd(&g.hist[bits >> 16], 1u);
    }
}

// ---------------- software grid barrier (all 148 blocks resident) -----------
__device__ __forceinline__ void gbar(int which) {
    __syncthreads();
    if (threadIdx.x == 0) {
        __threadfence();
        unsigned arrived = atomicAdd(&g.bars[which], 1u) + 1u;
        if (arrived < NBLK) {
            volatile unsigned* c = &g.bars[which];
            while (*c < NBLK) __nanosleep(64);
        }
        __threadfence();
    }
    __syncthreads();
}

// ---------------- K2: mega — scan/compact/rank+decode/mask/nms --------------
__global__ void __launch_bounds__(1024, 1)
k_mega(const float* __restrict__ reg, float* __restrict__ out) {
    __shared__ unsigned su[PBINS];
    __shared__ unsigned so[PBINS];
    __shared__ unsigned swsum[32];
    __shared__ int      s_pstar;
    __shared__ unsigned s_above;
    __shared__ unsigned remv[32];
    __shared__ unsigned keepw[32];

    const int tid = threadIdx.x;
    const int blk = blockIdx.x;
    const int gt  = blk * 1024 + tid;

    // ---- S0: per-part histogram sums (blocks 0..63) ----
    if (blk < NPART) {
        unsigned v = g.hist[blk * PBINS + tid];
        #pragma unroll
        for (int off = 16; off; off >>= 1) v += __shfl_xor_sync(0xffffffffu, v, off);
        if ((tid & 31) == 0) swsum[tid >> 5] = v;
        __syncthreads();
        if (tid < 32) {
            unsigned w = swsum[tid];
            #pragma unroll
            for (int off = 16; off; off >>= 1) w += __shfl_xor_sync(0xffffffffu, w, off);
            if (tid == 0) d_part[blk] = w;
        }
    }
    gbar(0);

    // ---- S1: block 0 finds the exact 16-bit threshold bin ----
    if (blk == 0) {
        if (tid == 0) {
            unsigned cum = 0; int ps = 0; unsigned ab = 0;
            for (int p = NPART - 1; p >= 0; --p) {
                unsigned pv = d_part[p];
                if (cum + pv >= TOPK) { ps = p; ab = cum; break; }
                cum += pv;
            }
            s_pstar = ps; s_above = ab;
        }
        __syncthreads();
        int base = s_pstar * PBINS;
        unsigned own = g.hist[base + tid];
        su[tid] = own; so[tid] = own;
        __syncthreads();
        for (int off = 1; off < PBINS; off <<= 1) {
            unsigned vv = (tid + off < PBINS) ? so[tid + off] : 0u;
            __syncthreads();
            so[tid] += vv;
            __syncthreads();
        }
        unsigned tot = s_above + so[tid];
        unsigned abv = tot - own;
        if (abv < TOPK && tot >= TOPK) d_thresh = base + tid;
    }
    gbar(1);

    // ---- S2: compact candidates (grid-stride over uint4 of sbits) ----
    {
        int th = d_thresh;
        for (int t = gt; t < N_ANCH / 4; t += NBLK * 1024) {
            uint4 s = reinterpret_cast<const uint4*>(d_sbits)[t];
            unsigned a = (unsigned)t * 4u;
            #pragma unroll
            for (int q = 0; q < 4; ++q) {
                unsigned bits = (q == 0) ? s.x : (q == 1) ? s.y : (q == 2) ? s.z : s.w;
                if ((int)(bits >> 16) >= th) {
                    int pos = atomicAdd(&g.count, 1);
                    if (pos < CAP) {
                        unsigned long long key =
                            ((unsigned long long)bits << 32) |
                            (unsigned long long)(0xFFFFFFFFu - (a + q));
                        d_keys[pos] = ~key;
                    }
                }
            }
        }
    }
    gbar(2);

    // ---- S3: rank-by-counting + decode (16 threads per candidate) ----
    {
        int M = g.count; if (M > CAP) M = CAP;
        int cand = gt >> 4;
        int sub  = gt & 15;
        if (cand < M) {
            unsigned long long key = d_keys[cand];
            int rank = 0;
            for (int k = sub; k < M; k += 16)
                rank += (d_keys[k] < key) ? 1 : 0;
            rank += __shfl_xor_sync(0xffffffffu, rank, 1);
            rank += __shfl_xor_sync(0xffffffffu, rank, 2);
            rank += __shfl_xor_sync(0xffffffffu, rank, 4);
            rank += __shfl_xor_sync(0xffffffffu, rank, 8);

            if (sub == 0 && rank < TOPK) {
                unsigned long long k0 = ~key;
                unsigned bits = (unsigned)(k0 >> 32);
                unsigned aidx = 0xFFFFFFFFu - (unsigned)(k0 & 0xFFFFFFFFull);
                float score = __uint_as_float(bits);
                int   lab   = (int)d_label[aidx];

                const float CLAMPF = 6.907755278982137f;   // log(1000)
                float4 r4 = reinterpret_cast<const float4*>(reg)[aidx];
                float e0 = __nv_expf(fminf(r4.x, CLAMPF));
                float e1 = __nv_expf(fminf(r4.y, CLAMPF));
                float e2 = __nv_expf(fminf(r4.z, CLAMPF));
                float e3 = __nv_expf(fminf(r4.w, CLAMPF));
                float ax = (float)(aidx % FMP);
                float ay = (float)(aidx / FMP);
                float b0 = fminf(1.0f, fmaxf(0.0f, __fdiv_rn(__fmul_rn(__fadd_rn(ax, -e0), 4.0f), 1280.0f)));
                float b1 = fminf(1.0f, fmaxf(0.0f, __fdiv_rn(__fmul_rn(__fadd_rn(ay, -e1), 4.0f), 1280.0f)));
                float b2 = fminf(1.0f, fmaxf(0.0f, __fdiv_rn(__fmul_rn(__fadd_rn(ax,  e2), 4.0f), 1280.0f)));
                float b3 = fminf(1.0f, fmaxf(0.0f, __fdiv_rn(__fmul_rn(__fadd_rn(ay,  e3), 4.0f), 1280.0f)));

                out[rank]        = score;
                out[TOPK + rank] = (float)lab;
                reinterpret_cast<float4*>(out + 2 * TOPK)[rank] = make_float4(b0, b1, b2, b3);
                d_boxes4[rank] = make_float4(b0, b1, b2, b3);
                d_tlab[rank]   = lab;
            }
        }
    }
    gbar(3);

    // ---- S4: suppression bitmask (grid-stride over rows i) ----
    for (int i = blk; i < TOPK; i += NBLK) {
        int w = tid >> 5;
        if (w >= (i >> 5)) {                  // lower words never read by NMS
            int j = tid;
            float4 bxi = d_boxes4[i];
            float ai = __fmul_rn(__fadd_rn(bxi.z, -bxi.x), __fadd_rn(bxi.w, -bxi.y));
            int li = d_tlab[i];

            bool sup = false;
            if (j < TOPK && j > i && d_tlab[j] == li) {
                float4 bxj = d_boxes4[j];
                float aj = __fmul_rn(__fadd_rn(bxj.z, -bxj.x), __fadd_rn(bxj.w, -bxj.y));
                float wd = fmaxf(1e-10f, __fadd_rn(fminf(bxi.z, bxj.z), -fmaxf(bxi.x, bxj.x)));
                float hd = fmaxf(1e-10f, __fadd_rn(fminf(bxi.w, bxj.w), -fmaxf(bxi.y, bxj.y)));
                float inter = __fmul_rn(wd, hd);
                float den = __fadd_rn(__fadd_rn(__fadd_rn(ai, aj), -inter), 1e-10f);
                // rn32(inter/den) > 0.6f  <=>  inter/den > midpoint(0.6f, nextup)
                sup = ((double)inter / (double)den) > 0.6000000536441802978515625;
            }
            unsigned b = __ballot_sync(0xffffffffu, sup);
            if ((j & 31) == 0) d_mask[i * 32 + w] = b;
        }
    }
    gbar(4);

    // ---- S5: greedy NMS (block 0 only; sparse serial + parallel cross-OR) --
    if (blk != 0) return;
    {
        int w = tid >> 5, ln = tid & 31;
        if (tid < 32) remv[tid] = 0u;
        __syncthreads();

        for (int c = 0; c < 32; ++c) {
            int row = c * 32 + ln;
            unsigned cval = 0u;
            if (w > c && row < TOPK) cval = d_mask[row * 32 + w];

            if (w == 0) {
                unsigned mself = (row < TOPK) ? d_mask[row * 32 + c] : 0u;
                unsigned r = remv[c];
                unsigned act = __ballot_sync(0xffffffffu, mself != 0u);
                while (act) {
                    int t = __ffs(act) - 1;
                    act &= act - 1u;
                    unsigned mv = __shfl_sync(0xffffffffu, mself, t);
                    r |= mv & (((r >> t) & 1u) - 1u);
                }
                if (ln == 0) keepw[c] = ~r;
            }
            __syncthreads();

            if (w > c) {
                unsigned kv = keepw[c];
                unsigned vv = ((kv >> ln) & 1u) ? cval : 0u;
                #pragma unroll
                for (int off = 16; off; off >>= 1)
                    vv |= __shfl_xor_sync(0xffffffffu, vv, off);
                if (ln == 0) remv[w] |= vv;
            }
            __syncthreads();
        }

        if (tid < TOPK)
            out[6 * TOPK + tid] = (float)((keepw[tid >> 5] >> (tid & 31)) & 1u);
    }
}

// ---------------- launch ----------------
extern "C" void kernel_launch(void* const* d_in, const int* in_sizes, int n_in,
                              void* d_out, int out_size) {
    const float* hmp = (const float*)d_in[0];
    const float* reg = (const float*)d_in[1];
    const float* iou = (const float*)d_in[2];
    float* out = (float*)d_out;

    void* gptr = nullptr;
    cudaGetSymbolAddress(&gptr, g);
    cudaMemsetAsync(gptr, 0, sizeof(GState), 0);

    k_score<<<N_ANCH / 8, 256>>>(hmp, iou);
    k_mega<<<NBLK, 1024>>>(reg, out);
}